// round 2
// baseline (speedup 1.0000x reference)
#include <cuda_runtime.h>
#include <math.h>

// TopKTokenChoiceRouter: logits = x(T,4096) @ W(64,4096)^T ; softmax ; top-2.
// Output layout: [weights (T,2) fp32][indices (T,2) as fp32].
// f32x2 packed-FMA GEMM, k-pair accumulation (operands naturally packed from LDS.128).

#define HS      4096
#define NEXP    64
#define TM      64
#define KC      32
#define NT      (HS / KC)      // 128
#define THREADS 256
#define RS      36             // smem row stride (floats): 144B, 16B-aligned, phase-conflict-free

typedef unsigned long long ull;

__device__ __forceinline__ ull pack2(float lo, float hi) {
    ull r;
    asm("mov.b64 %0, {%1, %2};" : "=l"(r) : "f"(lo), "f"(hi));
    return r;
}
__device__ __forceinline__ void fma2(ull& d, ull a, ull b) {
    asm("fma.rn.f32x2 %0, %1, %2, %0;" : "+l"(d) : "l"(a), "l"(b));
}
__device__ __forceinline__ float2 unpack2(ull v) {
    float2 f;
    asm("mov.b64 {%0, %1}, %2;" : "=f"(f.x), "=f"(f.y) : "l"(v));
    return f;
}

__global__ __launch_bounds__(THREADS)
void router_kernel(const float* __restrict__ x,
                   const float* __restrict__ W,
                   float* __restrict__ out,
                   int T)
{
    __shared__ float xs[2][TM][RS];     // 18.4 KB
    __shared__ float ws[2][NEXP][RS];   // 18.4 KB

    const int tid  = threadIdx.x;
    // warp covers 8 token-groups x 4 expert-groups (reuse-friendly shape)
    const int tx = (tid & 7) | ((tid >> 2) & 8);          // bits {0,1,2,5}
    const int ty = ((tid >> 3) & 3) | ((tid >> 4) & 12);  // bits {3,4,6,7}
    const int tok0 = blockIdx.x * TM;

    // loader mapping: phase-conflict-free STS.128 / coalesced LDG.128
    const int lrow = tid >> 3;    // 0..31
    const int lcol = tid & 7;     // 0..7

    const float* xg = x + (long)(tok0 + lrow) * HS + lcol * 4;
    const float* wg = W + (long)lrow * HS + lcol * 4;

    ull acc[4][4];
#pragma unroll
    for (int i = 0; i < 4; i++)
#pragma unroll
        for (int j = 0; j < 4; j++) acc[i][j] = pack2(0.0f, 0.0f);

    float4 rx[2], rw[2];

    // prologue: tile 0
#pragma unroll
    for (int p = 0; p < 2; p++) {
        rx[p] = *(const float4*)(xg + (long)(32 * p) * HS);
        rw[p] = *(const float4*)(wg + (long)(32 * p) * HS);
    }
#pragma unroll
    for (int p = 0; p < 2; p++) {
        *(float4*)&xs[0][lrow + 32 * p][lcol * 4] = rx[p];
        *(float4*)&ws[0][lrow + 32 * p][lcol * 4] = rw[p];
    }
    __syncthreads();

    for (int kt = 0; kt < NT; kt++) {
        const int b = kt & 1;
        if (kt + 1 < NT) {
            const int kb = (kt + 1) * KC;
#pragma unroll
            for (int p = 0; p < 2; p++) {
                rx[p] = *(const float4*)(xg + (long)(32 * p) * HS + kb);
                rw[p] = *(const float4*)(wg + (long)(32 * p) * HS + kb);
            }
        }

#pragma unroll
        for (int k4 = 0; k4 < KC / 4; k4++) {
            ull xp[4][2], wp[4][2];
#pragma unroll
            for (int i = 0; i < 4; i++) {
                const float4 v = *(const float4*)&xs[b][tx * 4 + i][k4 * 4];
                xp[i][0] = pack2(v.x, v.y);
                xp[i][1] = pack2(v.z, v.w);
            }
#pragma unroll
            for (int j = 0; j < 4; j++) {
                const float4 v = *(const float4*)&ws[b][ty * 4 + j][k4 * 4];
                wp[j][0] = pack2(v.x, v.y);
                wp[j][1] = pack2(v.z, v.w);
            }
#pragma unroll
            for (int i = 0; i < 4; i++)
#pragma unroll
                for (int j = 0; j < 4; j++) {
                    fma2(acc[i][j], xp[i][0], wp[j][0]);
                    fma2(acc[i][j], xp[i][1], wp[j][1]);
                }
        }

        if (kt + 1 < NT) {
#pragma unroll
            for (int p = 0; p < 2; p++) {
                *(float4*)&xs[b ^ 1][lrow + 32 * p][lcol * 4] = rx[p];
                *(float4*)&ws[b ^ 1][lrow + 32 * p][lcol * 4] = rw[p];
            }
        }
        __syncthreads();
    }

    // ---- epilogue: logits -> smem, softmax + top-2 ----
    float* lsm = &xs[0][0][0];   // 64*65 = 4160 floats <= 2*64*36 = 4608
#pragma unroll
    for (int i = 0; i < 4; i++)
#pragma unroll
        for (int j = 0; j < 4; j++) {
            const float2 v = unpack2(acc[i][j]);
            lsm[(tx * 4 + i) * 65 + (ty * 4 + j)] = v.x + v.y;
        }
    __syncthreads();

    if (tid < TM) {
        const int t = tid;
        float m1 = -INFINITY, m2 = -INFINITY;
        int   i1 = 0, i2 = 0;
#pragma unroll 8
        for (int e = 0; e < NEXP; e++) {
            const float v = lsm[t * 65 + e];
            if (v > m1) { m2 = m1; i2 = i1; m1 = v; i1 = e; }
            else if (v > m2) { m2 = v; i2 = e; }
        }
        float s = 0.0f;
#pragma unroll 8
        for (int e = 0; e < NEXP; e++)
            s += __expf(lsm[t * 65 + e] - m1);
        const float inv = 1.0f / s;
        const float w1 = inv;
        const float w2 = __expf(m2 - m1) * inv;

        const int tg = tok0 + t;
        out[2 * tg + 0] = w1;
        out[2 * tg + 1] = w2;
        out[2 * T + 2 * tg + 0] = (float)i1;
        out[2 * T + 2 * tg + 1] = (float)i2;
    }
}

extern "C" void kernel_launch(void* const* d_in, const int* in_sizes, int n_in,
                              void* d_out, int out_size)
{
    const float* x = (const float*)d_in[0];
    const float* W = (const float*)d_in[1];
    int sx = in_sizes[0];
    if (n_in >= 2 && in_sizes[0] < in_sizes[1]) {
        x = (const float*)d_in[1];
        W = (const float*)d_in[0];
        sx = in_sizes[1];
    }
    const int T = sx / HS;
    router_kernel<<<T / TM, THREADS>>>(x, W, (float*)d_out, T);
}

// round 4
// speedup vs baseline: 1.3374x; 1.3374x over previous
#include <cuda_runtime.h>
#include <math.h>

// TopKTokenChoiceRouter: logits = x(T,4096) @ W(64,4096)^T ; softmax ; top-2.
// Output layout: [weights (T,2) fp32][indices (T,2) as fp32].
// f32x2 packed-FMA GEMM, XOR-swizzled smem (conflict-free LDS.128).

#define HS      4096
#define NEXP    64
#define TM      64
#define KC      32
#define NT      (HS / KC)      // 128
#define THREADS 256

typedef unsigned long long ull;

__device__ __forceinline__ ull pack2(float lo, float hi) {
    ull r;
    asm("mov.b64 %0, {%1, %2};" : "=l"(r) : "f"(lo), "f"(hi));
    return r;
}
__device__ __forceinline__ void fma2(ull& d, ull a, ull b) {
    asm("fma.rn.f32x2 %0, %1, %2, %0;" : "+l"(d) : "l"(a), "l"(b));
}
__device__ __forceinline__ float2 unpack2(ull v) {
    float2 f;
    asm("mov.b64 {%0, %1}, %2;" : "=f"(f.x), "=f"(f.y) : "l"(v));
    return f;
}

// chunk slot for (row, chunk): XOR swizzle on row>>2 so microtile rows (stride 4)
// map to distinct bank-quads. Row stride = 32 floats (128B), no padding.
__device__ __forceinline__ int swz(int row, int chunk) {
    return row * KC + ((chunk ^ ((row >> 2) & 7)) << 2);
}

__global__ __launch_bounds__(THREADS)
void router_kernel(const float* __restrict__ x,
                   const float* __restrict__ W,
                   float* __restrict__ out,
                   int T)
{
    // one buffer: [ xs(2*64*32) | ws(2*64*32) ] = 32 KB; epilogue aliases front.
    __shared__ float sm[2 * TM * KC + 2 * NEXP * KC];
    float* xsb[2] = { sm,                sm + TM * KC };
    float* wsb[2] = { sm + 2 * TM * KC,  sm + 3 * TM * KC };

    const int tid  = threadIdx.x;
    // warp covers 8 token-groups x 4 expert-groups
    const int tx = (tid & 7) | ((tid >> 2) & 8);          // 0..15
    const int ty = ((tid >> 3) & 3) | ((tid >> 4) & 12);  // 0..15
    const int tok0 = blockIdx.x * TM;

    const int lrow = tid >> 3;    // 0..31
    const int lcol = tid & 7;     // 0..7

    const float* xg = x + (long)(tok0 + lrow) * HS + lcol * 4;
    const float* wg = W + (long)lrow * HS + lcol * 4;

    // precomputed swizzled store offsets (two row-batches)
    int soff[2];
#pragma unroll
    for (int p = 0; p < 2; p++) soff[p] = swz(lrow + 32 * p, lcol);

    ull acc[4][4];
#pragma unroll
    for (int i = 0; i < 4; i++)
#pragma unroll
        for (int j = 0; j < 4; j++) acc[i][j] = pack2(0.0f, 0.0f);

    float4 rx[2], rw[2];

    // prologue: tile 0
#pragma unroll
    for (int p = 0; p < 2; p++) {
        rx[p] = *(const float4*)(xg + (long)(32 * p) * HS);
        rw[p] = *(const float4*)(wg + (long)(32 * p) * HS);
    }
#pragma unroll
    for (int p = 0; p < 2; p++) {
        *(float4*)&xsb[0][soff[p]] = rx[p];
        *(float4*)&wsb[0][soff[p]] = rw[p];
    }
    __syncthreads();

    const int xsw = (tx & 7);   // swizzle key for this thread's token rows
    const int wsw = (ty & 7);

    for (int kt = 0; kt < NT; kt++) {
        const int b = kt & 1;
        if (kt + 1 < NT) {
            const int kb = (kt + 1) * KC;
#pragma unroll
            for (int p = 0; p < 2; p++) {
                rx[p] = *(const float4*)(xg + (long)(32 * p) * HS + kb);
                rw[p] = *(const float4*)(wg + (long)(32 * p) * HS + kb);
            }
        }

        const float* xsp = xsb[b];
        const float* wsp = wsb[b];
#pragma unroll
        for (int k4 = 0; k4 < KC / 4; k4++) {
            ull xp[4][2], wp[4][2];
#pragma unroll
            for (int i = 0; i < 4; i++) {
                const float4 v = *(const float4*)&xsp[(tx * 4 + i) * KC + ((k4 ^ xsw) << 2)];
                xp[i][0] = pack2(v.x, v.y);
                xp[i][1] = pack2(v.z, v.w);
            }
#pragma unroll
            for (int j = 0; j < 4; j++) {
                const float4 v = *(const float4*)&wsp[(ty * 4 + j) * KC + ((k4 ^ wsw) << 2)];
                wp[j][0] = pack2(v.x, v.y);
                wp[j][1] = pack2(v.z, v.w);
            }
#pragma unroll
            for (int i = 0; i < 4; i++)
#pragma unroll
                for (int j = 0; j < 4; j++) {
                    fma2(acc[i][j], xp[i][0], wp[j][0]);
                    fma2(acc[i][j], xp[i][1], wp[j][1]);
                }
        }

        if (kt + 1 < NT) {
#pragma unroll
            for (int p = 0; p < 2; p++) {
                *(float4*)&xsb[b ^ 1][soff[p]] = rx[p];
                *(float4*)&wsb[b ^ 1][soff[p]] = rw[p];
            }
        }
        __syncthreads();
    }

    // ---- epilogue: logits -> smem (stride 65), softmax + top-2 ----
    float* lsm = sm;   // 64*65 = 4160 floats, buffer holds 8192
#pragma unroll
    for (int i = 0; i < 4; i++)
#pragma unroll
        for (int j = 0; j < 4; j++) {
            const float2 v = unpack2(acc[i][j]);
            lsm[(tx * 4 + i) * 65 + (ty * 4 + j)] = v.x + v.y;
        }
    __syncthreads();

    if (tid < TM) {
        const int t = tid;
        float m1 = -INFINITY, m2 = -INFINITY;
        int   i1 = 0, i2 = 0;
#pragma unroll 8
        for (int e = 0; e < NEXP; e++) {
            const float v = lsm[t * 65 + e];
            if (v > m1) { m2 = m1; i2 = i1; m1 = v; i1 = e; }
            else if (v > m2) { m2 = v; i2 = e; }
        }
        float s = 0.0f;
#pragma unroll 8
        for (int e = 0; e < NEXP; e++)
            s += __expf(lsm[t * 65 + e] - m1);
        const float inv = 1.0f / s;
        const float w1 = inv;
        const float w2 = __expf(m2 - m1) * inv;

        const int tg = tok0 + t;
        out[2 * tg + 0] = w1;
        out[2 * tg + 1] = w2;
        out[2 * T + 2 * tg + 0] = (float)i1;
        out[2 * T + 2 * tg + 1] = (float)i2;
    }
}

extern "C" void kernel_launch(void* const* d_in, const int* in_sizes, int n_in,
                              void* d_out, int out_size)
{
    const float* x = (const float*)d_in[0];
    const float* W = (const float*)d_in[1];
    int sx = in_sizes[0];
    if (n_in >= 2 && in_sizes[0] < in_sizes[1]) {
        x = (const float*)d_in[1];
        W = (const float*)d_in[0];
        sx = in_sizes[1];
    }
    const int T = sx / HS;
    router_kernel<<<T / TM, THREADS>>>(x, W, (float*)d_out, T);
}

// round 5
// speedup vs baseline: 2.0118x; 1.5042x over previous
#include <cuda_runtime.h>
#include <math.h>

// TopKTokenChoiceRouter: logits = x(T,4096) @ W(64,4096)^T ; softmax ; top-2.
// Output layout: [weights (T,2) fp32][indices (T,2) as fp32].
// f32x2 packed-FMA GEMM, XOR-swizzled smem, 3-stage cp.async pipeline.

#define HS      4096
#define NEXP    64
#define TM      64
#define KC      32
#define NT      (HS / KC)      // 128
#define THREADS 256
#define NSTAGE  3
#define STAGEF  4096           // floats per stage: x 2048 + w 2048

typedef unsigned long long ull;

__device__ __forceinline__ void fma2(ull& d, ull a, ull b) {
    asm("fma.rn.f32x2 %0, %1, %2, %0;" : "+l"(d) : "l"(a), "l"(b));
}
__device__ __forceinline__ float2 unpack2(ull v) {
    float2 f;
    asm("mov.b64 {%0, %1}, %2;" : "=f"(f.x), "=f"(f.y) : "l"(v));
    return f;
}
__device__ __forceinline__ void cp16(float* dst_s, const float* src_g) {
    unsigned saddr = (unsigned)__cvta_generic_to_shared(dst_s);
    asm volatile("cp.async.cg.shared.global [%0], [%1], 16;\n"
                 :: "r"(saddr), "l"(src_g));
}
__device__ __forceinline__ void cp_commit() {
    asm volatile("cp.async.commit_group;\n");
}
template <int N>
__device__ __forceinline__ void cp_wait() {
    asm volatile("cp.async.wait_group %0;\n" :: "n"(N));
}

// chunk slot for (row, chunk): XOR swizzle on row>>2 so microtile rows (stride 4)
// map to distinct bank-quads. Row stride = 32 floats (128B), no padding.
__device__ __forceinline__ int swz(int row, int chunk) {
    return row * KC + ((chunk ^ ((row >> 2) & 7)) << 2);
}

__global__ __launch_bounds__(THREADS)
void router_kernel(const float* __restrict__ x,
                   const float* __restrict__ W,
                   float* __restrict__ out,
                   int T)
{
    __shared__ float sm[NSTAGE * STAGEF];   // 48 KB exactly

    const int tid  = threadIdx.x;
    // warp covers 8 token-groups x 4 expert-groups
    const int tx = (tid & 7) | ((tid >> 2) & 8);          // 0..15
    const int ty = ((tid >> 3) & 3) | ((tid >> 4) & 12);  // 0..15
    const int tok0 = blockIdx.x * TM;

    const int lrow = tid >> 3;    // 0..31
    const int lcol = tid & 7;     // 0..7

    const float* xg = x + (long)(tok0 + lrow) * HS + lcol * 4;
    const float* wg = W + (long)lrow * HS + lcol * 4;

    int soff[2];
#pragma unroll
    for (int p = 0; p < 2; p++) soff[p] = swz(lrow + 32 * p, lcol);

    // issue one stage of async loads (x tile + w tile), 4 x 16B per thread
    auto issue = [&](int kt) {
        const int s = kt % NSTAGE;
        const int kb = kt * KC;
        float* xs = sm + s * STAGEF;
        float* ws = xs + TM * KC;
#pragma unroll
        for (int p = 0; p < 2; p++) {
            cp16(&xs[soff[p]], xg + (long)(32 * p) * HS + kb);
            cp16(&ws[soff[p]], wg + (long)(32 * p) * HS + kb);
        }
        cp_commit();
    };

    ull acc[4][4];
#pragma unroll
    for (int i = 0; i < 4; i++)
#pragma unroll
        for (int j = 0; j < 4; j++) acc[i][j] = 0ull;

    issue(0);
    issue(1);

    const int xsw = (tx & 7);
    const int wsw = (ty & 7);

    for (int kt = 0; kt < NT; kt++) {
        cp_wait<1>();          // stage kt complete (<=1 groups still pending)
        __syncthreads();       // make it visible across threads

        if (kt + 2 < NT) issue(kt + 2);   // into buffer computed 1 iter ago — safe

        const float* xsp = sm + (kt % NSTAGE) * STAGEF;
        const float* wsp = xsp + TM * KC;

#pragma unroll
        for (int k4 = 0; k4 < KC / 4; k4++) {
            ulonglong2 xp[4], wp[4];
#pragma unroll
            for (int i = 0; i < 4; i++)
                xp[i] = *(const ulonglong2*)&xsp[(tx * 4 + i) * KC + ((k4 ^ xsw) << 2)];
#pragma unroll
            for (int j = 0; j < 4; j++)
                wp[j] = *(const ulonglong2*)&wsp[(ty * 4 + j) * KC + ((k4 ^ wsw) << 2)];
#pragma unroll
            for (int i = 0; i < 4; i++)
#pragma unroll
                for (int j = 0; j < 4; j++) {
                    fma2(acc[i][j], xp[i].x, wp[j].x);
                    fma2(acc[i][j], xp[i].y, wp[j].y);
                }
        }
        __syncthreads();       // all reads of this stage done before its buffer is refilled
    }

    // ---- epilogue: logits -> smem (stride 65), softmax + top-2 ----
    float* lsm = sm;   // 64*65 = 4160 floats <= 12288
#pragma unroll
    for (int i = 0; i < 4; i++)
#pragma unroll
        for (int j = 0; j < 4; j++) {
            const float2 v = unpack2(acc[i][j]);
            lsm[(tx * 4 + i) * 65 + (ty * 4 + j)] = v.x + v.y;
        }
    __syncthreads();

    if (tid < TM) {
        const int t = tid;
        float m1 = -INFINITY, m2 = -INFINITY;
        int   i1 = 0, i2 = 0;
#pragma unroll 8
        for (int e = 0; e < NEXP; e++) {
            const float v = lsm[t * 65 + e];
            if (v > m1) { m2 = m1; i2 = i1; m1 = v; i1 = e; }
            else if (v > m2) { m2 = v; i2 = e; }
        }
        float s = 0.0f;
#pragma unroll 8
        for (int e = 0; e < NEXP; e++)
            s += __expf(lsm[t * 65 + e] - m1);
        const float inv = 1.0f / s;
        const float w1 = inv;
        const float w2 = __expf(m2 - m1) * inv;

        const int tg = tok0 + t;
        out[2 * tg + 0] = w1;
        out[2 * tg + 1] = w2;
        out[2 * T + 2 * tg + 0] = (float)i1;
        out[2 * T + 2 * tg + 1] = (float)i2;
    }
}

extern "C" void kernel_launch(void* const* d_in, const int* in_sizes, int n_in,
                              void* d_out, int out_size)
{
    const float* x = (const float*)d_in[0];
    const float* W = (const float*)d_in[1];
    int sx = in_sizes[0];
    if (n_in >= 2 && in_sizes[0] < in_sizes[1]) {
        x = (const float*)d_in[1];
        W = (const float*)d_in[0];
        sx = in_sizes[1];
    }
    const int T = sx / HS;
    router_kernel<<<T / TM, THREADS>>>(x, W, (float*)d_out, T);
}

// round 6
// speedup vs baseline: 2.5550x; 1.2701x over previous
#include <cuda_runtime.h>
#include <math.h>

// TopKTokenChoiceRouter: logits = x(T,4096) @ W(64,4096)^T ; softmax ; top-2.
// Output layout: [weights (T,2) fp32][indices (T,2) as fp32].
// Split-K x4 f32x2 GEMM (partials to scratch) + warp-per-token reduce kernel.

#define HS      4096
#define NEXP    64
#define TM      64
#define KC      32
#define NSPLIT  4
#define KPS     (HS / NSPLIT)      // 1024 per split
#define NT      (KPS / KC)         // 32 tiles per CTA
#define THREADS 256
#define NSTAGE  3
#define STAGEF  4096
#define TTOT    8192

__device__ float g_partial[NSPLIT * TTOT * NEXP];   // 8.4 MB scratch

typedef unsigned long long ull;

__device__ __forceinline__ void fma2(ull& d, ull a, ull b) {
    asm("fma.rn.f32x2 %0, %1, %2, %0;" : "+l"(d) : "l"(a), "l"(b));
}
__device__ __forceinline__ float2 unpack2(ull v) {
    float2 f;
    asm("mov.b64 {%0, %1}, %2;" : "=f"(f.x), "=f"(f.y) : "l"(v));
    return f;
}
__device__ __forceinline__ void cp16(float* dst_s, const float* src_g) {
    unsigned saddr = (unsigned)__cvta_generic_to_shared(dst_s);
    asm volatile("cp.async.cg.shared.global [%0], [%1], 16;\n"
                 :: "r"(saddr), "l"(src_g));
}
__device__ __forceinline__ void cp_commit() {
    asm volatile("cp.async.commit_group;\n");
}
template <int N>
__device__ __forceinline__ void cp_wait() {
    asm volatile("cp.async.wait_group %0;\n" :: "n"(N));
}

__device__ __forceinline__ int swz(int row, int chunk) {
    return row * KC + ((chunk ^ ((row >> 2) & 7)) << 2);
}

// ---------------- GEMM partial kernel ----------------
__global__ __launch_bounds__(THREADS, 3)
void router_gemm(const float* __restrict__ x,
                 const float* __restrict__ W)
{
    __shared__ float sm[NSTAGE * STAGEF];   // 48 KB

    const int tid  = threadIdx.x;
    const int tx = (tid & 7) | ((tid >> 2) & 8);
    const int ty = ((tid >> 3) & 3) | ((tid >> 4) & 12);
    const int tok0  = blockIdx.x * TM;
    const int split = blockIdx.y;
    const int kbase = split * KPS;

    const int lrow = tid >> 3;
    const int lcol = tid & 7;

    const float* xg = x + (long)(tok0 + lrow) * HS + kbase + lcol * 4;
    const float* wg = W + (long)lrow * HS + kbase + lcol * 4;

    int soff[2];
#pragma unroll
    for (int p = 0; p < 2; p++) soff[p] = swz(lrow + 32 * p, lcol);

    auto issue = [&](int kt) {
        const int s = kt % NSTAGE;
        const int kb = kt * KC;
        float* xs = sm + s * STAGEF;
        float* ws = xs + TM * KC;
#pragma unroll
        for (int p = 0; p < 2; p++) {
            cp16(&xs[soff[p]], xg + (long)(32 * p) * HS + kb);
            cp16(&ws[soff[p]], wg + (long)(32 * p) * HS + kb);
        }
        cp_commit();
    };

    ull acc[4][4];
#pragma unroll
    for (int i = 0; i < 4; i++)
#pragma unroll
        for (int j = 0; j < 4; j++) acc[i][j] = 0ull;

    issue(0);
    issue(1);

    const int xsw = (tx & 7);
    const int wsw = (ty & 7);

    for (int kt = 0; kt < NT; kt++) {
        cp_wait<1>();
        __syncthreads();

        if (kt + 2 < NT) issue(kt + 2);

        const float* xsp = sm + (kt % NSTAGE) * STAGEF;
        const float* wsp = xsp + TM * KC;

#pragma unroll
        for (int k4 = 0; k4 < KC / 4; k4++) {
            ulonglong2 xp[4], wp[4];
#pragma unroll
            for (int i = 0; i < 4; i++)
                xp[i] = *(const ulonglong2*)&xsp[(tx * 4 + i) * KC + ((k4 ^ xsw) << 2)];
#pragma unroll
            for (int j = 0; j < 4; j++)
                wp[j] = *(const ulonglong2*)&wsp[(ty * 4 + j) * KC + ((k4 ^ wsw) << 2)];
#pragma unroll
            for (int i = 0; i < 4; i++)
#pragma unroll
                for (int j = 0; j < 4; j++) {
                    fma2(acc[i][j], xp[i].x, wp[j].x);
                    fma2(acc[i][j], xp[i].y, wp[j].y);
                }
        }
        __syncthreads();
    }

    // stage logits (stride 65), then coalesced partial store
    float* lsm = sm;
#pragma unroll
    for (int i = 0; i < 4; i++)
#pragma unroll
        for (int j = 0; j < 4; j++) {
            const float2 v = unpack2(acc[i][j]);
            lsm[(tx * 4 + i) * 65 + (ty * 4 + j)] = v.x + v.y;
        }
    __syncthreads();

    float* dst = g_partial + ((long)split * TTOT + tok0) * NEXP;
#pragma unroll
    for (int idx = tid; idx < TM * NEXP; idx += THREADS) {
        const int t = idx >> 6;
        const int e = idx & 63;
        dst[idx] = lsm[t * 65 + e];
    }
}

// ---------------- reduce + softmax + top-2 kernel ----------------
// one warp per token; lane l owns experts l and l+32
__global__ __launch_bounds__(256)
void router_reduce(float* __restrict__ out, int T)
{
    const int wid = threadIdx.x >> 5;
    const int l   = threadIdx.x & 31;
    const int t   = blockIdx.x * 8 + wid;
    if (t >= T) return;

    const float* p = g_partial + (long)t * NEXP + l;
    float v0 = 0.0f, v1 = 0.0f;
#pragma unroll
    for (int s = 0; s < NSPLIT; s++) {
        v0 += p[(long)s * TTOT * NEXP];
        v1 += p[(long)s * TTOT * NEXP + 32];
    }

    // global max
    float m = fmaxf(v0, v1);
#pragma unroll
    for (int o = 16; o > 0; o >>= 1)
        m = fmaxf(m, __shfl_xor_sync(0xffffffffu, m, o));

    // sum of exp
    float se = __expf(v0 - m) + __expf(v1 - m);
#pragma unroll
    for (int o = 16; o > 0; o >>= 1)
        se += __shfl_xor_sync(0xffffffffu, se, o);

    // local sorted top-2 (value desc, index asc on ties -> v0 first unless v1 strictly greater)
    float a1, a2; int i1, i2;
    if (v1 > v0) { a1 = v1; i1 = l + 32; a2 = v0; i2 = l; }
    else         { a1 = v0; i1 = l;      a2 = v1; i2 = l + 32; }

    // butterfly merge of sorted pairs
#pragma unroll
    for (int o = 16; o > 0; o >>= 1) {
        const float b1 = __shfl_xor_sync(0xffffffffu, a1, o);
        const int  bi1 = __shfl_xor_sync(0xffffffffu, i1, o);
        const float b2 = __shfl_xor_sync(0xffffffffu, a2, o);
        const int  bi2 = __shfl_xor_sync(0xffffffffu, i2, o);

        const bool afirst = (a1 > b1) || (a1 == b1 && i1 < bi1);
        float r1, r2; int ri1, ri2;
        if (afirst) {
            r1 = a1; ri1 = i1;
            const bool asecond = (a2 > b1) || (a2 == b1 && i2 < bi1);
            if (asecond) { r2 = a2; ri2 = i2; } else { r2 = b1; ri2 = bi1; }
        } else {
            r1 = b1; ri1 = bi1;
            const bool bsecond = (b2 > a1) || (b2 == a1 && bi2 < i1);
            if (bsecond) { r2 = b2; ri2 = bi2; } else { r2 = a1; ri2 = i1; }
        }
        a1 = r1; i1 = ri1; a2 = r2; i2 = ri2;
    }

    if (l == 0) {
        const float inv = 1.0f / se;
        out[2 * t + 0] = __expf(a1 - m) * inv;   // a1 == m -> exp(0)
        out[2 * t + 1] = __expf(a2 - m) * inv;
        out[2 * T + 2 * t + 0] = (float)i1;
        out[2 * T + 2 * t + 1] = (float)i2;
    }
}

extern "C" void kernel_launch(void* const* d_in, const int* in_sizes, int n_in,
                              void* d_out, int out_size)
{
    const float* x = (const float*)d_in[0];
    const float* W = (const float*)d_in[1];
    int sx = in_sizes[0];
    if (n_in >= 2 && in_sizes[0] < in_sizes[1]) {
        x = (const float*)d_in[1];
        W = (const float*)d_in[0];
        sx = in_sizes[1];
    }
    const int T = sx / HS;   // 8192

    dim3 grid(T / TM, NSPLIT);
    router_gemm<<<grid, THREADS>>>(x, W);
    router_reduce<<<(T + 7) / 8, 256>>>((float*)d_out, T);
}